// round 11
// baseline (speedup 1.0000x reference)
#include <cuda_runtime.h>
#include <float.h>

typedef unsigned long long ull;

#define NB   8
#define NLQ  512
#define NL   4096
#define ND   64
#define TQ   16
#define NTHREADS 512
#define NCTAS  (NB * (NLQ/TQ))     // 256

#define TKS 128                    // score-group tile
#define NTS (NL/TKS)               // 32
#define TKM 64                     // mean-group tile
#define NTM (NL/TKM)               // 64

#define KSTR 68          // split-d row: d<32 at [d], d>=32 at [36+(d-32)]
#define KBUF (TKS*KSTR)  // 8704
#define VSTR 64
#define QTH  648         // qT d-half block stride (32*20 + 8)
#define NWORDS (NL/32)   // 128 mask words per row

// smem offsets (floats)
#define OFF_KS   0                             // 2*8704 = 17408
#define OFF_VS   (OFF_KS + 2*KBUF)             // 2*64*64 = 8192
#define OFF_KM   (OFF_VS + 2*TKM*VSTR)         // 128 words
#define OFF_VM   (OFF_KM + 128)                // 64 words
#define OFF_QT   (OFF_VM + 64)                 // 1296
#define OFF_MSUM (OFF_QT + 2*QTH)              // 1024
#define OFF_CNT  (OFF_MSUM + TQ*ND)            // 16
#define SMEM_FLOATS (OFF_CNT + TQ)             // 28128
#define SMEM_BYTES  (SMEM_FLOATS * 4)          // 112512 -> 2 CTAs/SM

// packed fp32x2 ops (sm_103a)
#define F32X2_FMA(d,a,b)  asm("fma.rn.f32x2 %0, %1, %2, %0;" : "+l"(d) : "l"(a), "l"(b))
#define F32X2_ADD(d,a,b)  asm("add.rn.f32x2 %0, %1, %2;"     : "=l"(d) : "l"(a), "l"(b))
#define F32X2_PACK(d,lo,hi)   asm("mov.b64 %0, {%1, %2};" : "=l"(d) : "f"(lo), "f"(hi))
#define F32X2_UNPACK(lo,hi,s) asm("mov.b64 {%0, %1}, %2;" : "=f"(lo), "=f"(hi) : "l"(s))
// predicated packed accumulate: if (bit) { a += x; b += y; }
#define F32X2_PADD2(a,b,x,y,bit) \
    asm("{\n\t.reg .pred p;\n\tsetp.ne.u32 p, %4, 0;\n\t" \
        "@p add.rn.f32x2 %0, %0, %2;\n\t@p add.rn.f32x2 %1, %1, %3;\n\t}" \
        : "+l"(a), "+l"(b) : "l"(x), "l"(y), "r"(bit))

__device__ __forceinline__ void cp16(void* s, const void* g) {
    unsigned sa = (unsigned)__cvta_generic_to_shared(s);
    asm volatile("cp.async.cg.shared.global [%0], [%1], 16;" :: "r"(sa), "l"(g));
}
__device__ __forceinline__ void cp8(void* s, const void* g) {
    unsigned sa = (unsigned)__cvta_generic_to_shared(s);
    asm volatile("cp.async.ca.shared.global [%0], [%1], 8;" :: "r"(sa), "l"(g));
}
#define CP_COMMIT() asm volatile("cp.async.commit_group;" ::: "memory")
#define CP_WAIT0()  asm volatile("cp.async.wait_group 0;" ::: "memory")
#define BARG(id)    asm volatile("bar.sync %0, 256;" :: "r"(id) : "memory")

// global scratch
__device__ float    g_sc[(size_t)NCTAS * TQ * NL];      // 64 MB (L2-resident per wave)
__device__ unsigned g_mbits[(size_t)NB * NLQ * NWORDS]; // 2 MB bit mask
__device__ int      g_mask_mode;                        // 0=u8, 1=i32, 2=f32

__global__ void detect_mask_kernel(const unsigned int* __restrict__ m) {
    int lane = threadIdx.x;
    unsigned w = m[lane];
    int allle1 = __all_sync(0xffffffffu, w <= 1u);
    int allf   = __all_sync(0xffffffffu, w == 0u || w == 0x3F800000u);
    if (lane == 0) g_mask_mode = allf ? 2 : (allle1 ? 1 : 0);
}

// pack mask -> bits: one thread builds one 32-bit word
__global__ __launch_bounds__(256)
void maskbits_kernel(const void* __restrict__ mg) {
    int tid = blockIdx.x * 256 + threadIdx.x;      // 0 .. 524287
    unsigned w = 0;
    if (g_mask_mode == 0) {
        const uint4* p = (const uint4*)((const char*)mg + (size_t)tid * 32);
        uint4 a = p[0], b2 = p[1];
        unsigned v[8] = {a.x, a.y, a.z, a.w, b2.x, b2.y, b2.z, b2.w};
        #pragma unroll
        for (int i = 0; i < 8; ++i)
            #pragma unroll
            for (int j = 0; j < 4; ++j)
                w |= (((v[i] >> (8 * j)) & 0xFFu) ? 1u : 0u) << (i * 4 + j);
    } else {
        const uint4* p = (const uint4*)((const char*)mg + (size_t)tid * 128);
        #pragma unroll
        for (int i = 0; i < 8; ++i) {
            uint4 x = p[i];
            w |= (x.x ? 1u : 0u) << (i * 4 + 0);
            w |= (x.y ? 1u : 0u) << (i * 4 + 1);
            w |= (x.z ? 1u : 0u) << (i * 4 + 2);
            w |= (x.w ? 1u : 0u) << (i * 4 + 3);
        }
    }
    g_mbits[tid] = w;
}

__global__ __launch_bounds__(NTHREADS, 2)
void ga_kernel(const float* __restrict__ qg, const float* __restrict__ kg,
               const float* __restrict__ vg, float* __restrict__ out)
{
    extern __shared__ float smem[];
    float*    k_s  = smem + OFF_KS;
    float*    v_s  = smem + OFF_VS;
    unsigned* km   = (unsigned*)(smem + OFF_KM);
    unsigned* vm   = (unsigned*)(smem + OFF_VM);
    float*    qT   = smem + OFF_QT;
    float*    msum = smem + OFF_MSUM;
    float*    cnts = smem + OFF_CNT;

    const int t    = threadIdx.x;
    const int wid  = t >> 5;
    const int lane = t & 31;
    const int b    = blockIdx.x >> 5;          // 32 q-tiles per batch
    const int q0   = (blockIdx.x & 31) * TQ;

    float* gsc = g_sc + (size_t)blockIdx.x * (TQ * NL);
    const unsigned* mb = g_mbits + (size_t)(b * NLQ + q0) * NWORDS;

    float c0v[2] = {0.f, 0.f}, c1v[2] = {0.f, 0.f};

    if (wid < 8) {
        // =================== SCORE GROUP (threads 0..255) ===================
        const int t2 = t;
        // stage qT: qT[(d>>5)*QTH + (d&31)*20 + q], 1024 elems / 256 thr
        #pragma unroll
        for (int e = 0; e < 4; ++e) {
            int idx = t2 * 4 + e;
            int d = idx >> 4, q = idx & 15;
            qT[(d >> 5) * QTH + (d & 31) * 20 + q] =
                qg[((size_t)(b * NLQ + q0 + q)) * ND + d];
        }

        const char* kbase = (const char*)(kg + (size_t)b * NL * ND);
        const int pc   = t2 & 15;
        const int soff = (pc < 8) ? 4 * pc : 36 + 4 * (pc - 8);
        const int pr0  = t2 >> 4;

        {
            #pragma unroll
            for (int r = 0; r < 8; ++r) {
                int row = pr0 + 16 * r;
                cp16(k_s + row * KSTR + soff,
                     kbase + (size_t)row * 256 + pc * 16);
            }
            if (t2 < 16) cp16(km + t2 * 4, mb + t2 * NWORDS + 0);
            CP_COMMIT();
        }

        // lane layout: ks (8 key-pairs) x dh (2 dim-halves) x qq (2 q-halves)
        const int ks = lane >> 2;
        const int dh = (lane >> 1) & 1;
        const int qq = lane & 1;
        const int k0 = wid * 16 + 2 * ks;
        const int kword = wid >> 1;
        const int kb0sh = k0 & 31;                // bit of key k0 in its word
        const float* qb = qT + dh * QTH + qq * 8;

        for (int tile = 0; tile < NTS; ++tile) {
            CP_WAIT0();
            BARG(1);
            if (tile + 1 < NTS) {
                float* kd = k_s + ((tile + 1) & 1) * KBUF;
                const char* kt = kbase + (size_t)(tile + 1) * TKS * 256;
                #pragma unroll
                for (int r = 0; r < 8; ++r) {
                    int row = pr0 + 16 * r;
                    cp16(kd + row * KSTR + soff,
                         kt + (size_t)row * 256 + pc * 16);
                }
                if (t2 < 16)
                    cp16(km + ((tile + 1) & 1) * 64 + t2 * 4,
                         mb + t2 * NWORDS + (tile + 1) * 4);
                CP_COMMIT();
            }

            const float* kb0 = k_s + (tile & 1) * KBUF + k0 * KSTR + dh * 36;
            const float* kb1 = kb0 + KSTR;
            ull a00=0, a01=0, a02=0, a03=0, a10=0, a11=0, a12=0, a13=0;
            #pragma unroll
            for (int s = 0; s < 8; ++s) {
                float4 ka = *(const float4*)(kb0 + 4 * s);
                float4 kc = *(const float4*)(kb1 + 4 * s);
                #pragma unroll
                for (int j = 0; j < 4; ++j) {
                    const float* qrow = qb + (4 * s + j) * 20;
                    ulonglong2 qA = *(const ulonglong2*)qrow;
                    ulonglong2 qB = *(const ulonglong2*)(qrow + 4);
                    float fa = (j==0)?ka.x:(j==1)?ka.y:(j==2)?ka.z:ka.w;
                    float fc = (j==0)?kc.x:(j==1)?kc.y:(j==2)?kc.z:kc.w;
                    ull pa, pc2;
                    F32X2_PACK(pa, fa, fa);
                    F32X2_PACK(pc2, fc, fc);
                    F32X2_FMA(a00, pa, qA.x);  F32X2_FMA(a01, pa, qA.y);
                    F32X2_FMA(a02, pa, qB.x);  F32X2_FMA(a03, pa, qB.y);
                    F32X2_FMA(a10, pc2, qA.x); F32X2_FMA(a11, pc2, qA.y);
                    F32X2_FMA(a12, pc2, qB.x); F32X2_FMA(a13, pc2, qB.y);
                }
            }
            // reduce over dh (lane bit 1)
            ull o;
            o = __shfl_xor_sync(0xffffffffu, a00, 2); F32X2_ADD(a00, a00, o);
            o = __shfl_xor_sync(0xffffffffu, a01, 2); F32X2_ADD(a01, a01, o);
            o = __shfl_xor_sync(0xffffffffu, a02, 2); F32X2_ADD(a02, a02, o);
            o = __shfl_xor_sync(0xffffffffu, a03, 2); F32X2_ADD(a03, a03, o);
            o = __shfl_xor_sync(0xffffffffu, a10, 2); F32X2_ADD(a10, a10, o);
            o = __shfl_xor_sync(0xffffffffu, a11, 2); F32X2_ADD(a11, a11, o);
            o = __shfl_xor_sync(0xffffffffu, a12, 2); F32X2_ADD(a12, a12, o);
            o = __shfl_xor_sync(0xffffffffu, a13, 2); F32X2_ADD(a13, a13, o);
            if (dh == 0) {
                float f0[8], f1[8];
                F32X2_UNPACK(f0[0], f0[1], a00); F32X2_UNPACK(f0[2], f0[3], a01);
                F32X2_UNPACK(f0[4], f0[5], a02); F32X2_UNPACK(f0[6], f0[7], a03);
                F32X2_UNPACK(f1[0], f1[1], a10); F32X2_UNPACK(f1[2], f1[3], a11);
                F32X2_UNPACK(f1[4], f1[5], a12); F32X2_UNPACK(f1[6], f1[7], a13);
                const unsigned* kmc = km + (tile & 1) * 64;
                const int l0 = tile * TKS;
                #pragma unroll
                for (int qi = 0; qi < 8; ++qi) {
                    const int q = qq * 8 + qi;
                    unsigned w = kmc[q * 4 + kword];
                    float2 st;
                    st.x = ((w >> kb0sh) & 1u)       ? f0[qi] * 0.125f : -FLT_MAX;
                    st.y = ((w >> (kb0sh + 1)) & 1u) ? f1[qi] * 0.125f : -FLT_MAX;
                    *(float2*)(gsc + q * NL + l0 + k0) = st;
                }
            }
        }

        __threadfence_block();
        BARG(1);   // all scores written by score group

        // ---- top-32 + softmax + gather for queries wid, wid+8 ----
        #pragma unroll 1
        for (int half = 0; half < 2; ++half) {
            const int q = wid + 8 * half;
            const float* row = gsc + q * NL;

            float v0 = -FLT_MAX, v1 = -FLT_MAX, v2 = -FLT_MAX, v3 = -FLT_MAX;
            int   i0 = NL, i1 = NL, i2 = NL, i3 = NL;
            for (int i = lane; i < NL; i += 32) {
                float x = row[i];
                if (x > v3) {
                    if (x > v1) {
                        if (x > v0) { v3=v2;i3=i2; v2=v1;i2=i1; v1=v0;i1=i0; v0=x;i0=i; }
                        else        { v3=v2;i3=i2; v2=v1;i2=i1; v1=x;i1=i; }
                    } else {
                        if (x > v2) { v3=v2;i3=i2; v2=x;i2=i; }
                        else        { v3=x;i3=i; }
                    }
                }
            }

            float myval = -FLT_MAX;
            int   myidx = NL;
            for (int s = 0; s < 32; ++s) {
                float cv = v0; int ci = i0;
                #pragma unroll
                for (int off = 16; off; off >>= 1) {
                    float ov = __shfl_xor_sync(0xffffffffu, cv, off);
                    int   oi = __shfl_xor_sync(0xffffffffu, ci, off);
                    if (ov > cv || (ov == cv && oi < ci)) { cv = ov; ci = oi; }
                }
                if (lane == s) { myval = cv; myidx = ci; }
                if (v0 == cv && i0 == ci) {
                    v0 = v1; i0 = i1; v1 = v2; i1 = i2; v2 = v3; i2 = i3;
                    v3 = -FLT_MAX; i3 = NL;
                    if (v0 == -FLT_MAX && cv > -FLT_MAX) {
                        float nv = -FLT_MAX; int ni = NL;
                        for (int i = lane; i < NL; i += 32) {
                            float x = row[i];
                            if (x < cv && x > nv) { nv = x; ni = i; }
                        }
                        v0 = nv; i0 = ni;
                    }
                }
            }

            bool  valid = (myval > -1e37f) && (myidx < NL);
            float mmax  = valid ? myval : -FLT_MAX;
            #pragma unroll
            for (int off = 16; off; off >>= 1)
                mmax = fmaxf(mmax, __shfl_xor_sync(0xffffffffu, mmax, off));
            float e  = valid ? __expf(myval - mmax) : 0.f;
            float es = e;
            #pragma unroll
            for (int off = 16; off; off >>= 1)
                es += __shfl_xor_sync(0xffffffffu, es, off);
            float attn = (es > 0.f) ? e / es : 0.f;

            const float* vb = vg + (size_t)b * NL * ND;
            float cc0 = 0.f, cc1 = 0.f;
            #pragma unroll 4
            for (int i = 0; i < 32; ++i) {
                float a   = __shfl_sync(0xffffffffu, attn,  i);
                int   idx = __shfl_sync(0xffffffffu, myidx, i);
                if (a > 0.f && idx < NL) {
                    const float* vr2 = vb + (size_t)idx * ND;
                    cc0 += a * vr2[lane];
                    cc1 += a * vr2[lane + 32];
                }
            }
            c0v[half] = cc0;
            c1v[half] = cc1;
        }
    } else {
        // =================== MEAN GROUP (threads 256..511) ==================
        const int t2 = t - 256;
        const int wm = wid - 8;

        const char* vbase = (const char*)(vg + (size_t)b * NL * ND);
        const int fd4 = t2 & 15;
        const int fl0 = t2 >> 4;

        {
            #pragma unroll
            for (int r = 0; r < 4; ++r) {
                int row = fl0 + 16 * r;
                cp16(v_s + row * VSTR + fd4 * 4,
                     vbase + (size_t)row * 256 + fd4 * 16);
            }
            if (t2 < 16) cp8(vm + t2 * 2, mb + t2 * NWORDS + 0);
            CP_COMMIT();
        }

        const int c    = lane & 15;
        const int qg2  = (lane >> 4) * 8;        // 8 queries per lane-half
        const int lb   = wm * 8;                 // 8 rows per warp
        const int wsel = wm >> 2;                // word index for this warp's rows
        const int shb  = (wm * 8) & 31;

        ull accA[8] = {0,0,0,0,0,0,0,0}, accB[8] = {0,0,0,0,0,0,0,0};

        for (int tile = 0; tile < NTM; ++tile) {
            CP_WAIT0();
            BARG(2);
            if (tile + 1 < NTM) {
                float* vd = v_s + ((tile + 1) & 1) * (TKM * VSTR);
                const char* vt = vbase + (size_t)(tile + 1) * TKM * 256;
                #pragma unroll
                for (int r = 0; r < 4; ++r) {
                    int row = fl0 + 16 * r;
                    cp16(vd + row * VSTR + fd4 * 4,
                         vt + (size_t)row * 256 + fd4 * 16);
                }
                if (t2 < 16)
                    cp8(vm + ((tile + 1) & 1) * 32 + t2 * 2,
                        mb + t2 * NWORDS + (tile + 1) * 2);
                CP_COMMIT();
            }

            const float* vbuf = v_s + (tile & 1) * (TKM * VSTR);
            const unsigned* vmc = vm + (tile & 1) * 32;
            // per-query bit-bytes for this warp's 8 rows
            unsigned bq[8];
            #pragma unroll
            for (int j = 0; j < 8; ++j)
                bq[j] = (vmc[(qg2 + j) * 2 + wsel] >> shb) & 0xFFu;

            #pragma unroll
            for (int r = 0; r < 8; ++r) {
                ulonglong2 vv = *(const ulonglong2*)(vbuf + (lb + r) * VSTR + 4 * c);
                #pragma unroll
                for (int j = 0; j < 8; ++j)
                    F32X2_PADD2(accA[j], accB[j], vv.x, vv.y, bq[j] & (1u << r));
            }
        }

        // publish per-warp partials into v_s (mean group done with tiles)
        BARG(2);
        float* pbuf = v_s + wm * 1024;
        #pragma unroll
        for (int j = 0; j < 8; ++j) {
            float g0, g1, g2, g3;
            F32X2_UNPACK(g0, g1, accA[j]);
            F32X2_UNPACK(g2, g3, accB[j]);
            *(float4*)(pbuf + (qg2 + j) * ND + 4 * c) = make_float4(g0, g1, g2, g3);
        }
        BARG(2);
        // reduce partials -> msum (1024 elems / 256 threads)
        #pragma unroll
        for (int r = 0; r < 4; ++r) {
            const int jx = t2 + 256 * r;
            float s = 0.f;
            #pragma unroll
            for (int p = 0; p < 8; ++p) s += v_s[p * 1024 + jx];
            msum[jx] = s;
        }
        // counts via popc: warp wm handles queries wm, wm+8
        #pragma unroll
        for (int half = 0; half < 2; ++half) {
            const int q = wm + 8 * half;
            const unsigned* mrow = mb + q * NWORDS;
            unsigned s = __popc(mrow[lane]) + __popc(mrow[lane + 32]) +
                         __popc(mrow[lane + 64]) + __popc(mrow[lane + 96]);
            #pragma unroll
            for (int off = 16; off; off >>= 1)
                s += __shfl_xor_sync(0xffffffffu, s, off);
            if (lane == 0) cnts[q] = (float)s;
        }
    }

    __syncthreads();

    if (wid < 8) {
        #pragma unroll
        for (int half = 0; half < 2; ++half) {
            const int q = wid + 8 * half;
            float cdiv = fmaxf(cnts[q], 1.f);
            size_t orow = ((size_t)(b * NLQ + q0 + q)) * ND;
            out[orow + lane]      = msum[q * ND + lane]      / cdiv + c0v[half];
            out[orow + lane + 32] = msum[q * ND + lane + 32] / cdiv + c1v[half];
        }
    }
}

extern "C" void kernel_launch(void* const* d_in, const int* in_sizes, int n_in,
                              void* d_out, int out_size) {
    const float* q    = (const float*)d_in[0];
    const float* k    = (const float*)d_in[1];
    const float* v    = (const float*)d_in[2];
    const void*  mask = d_in[3];
    float* out = (float*)d_out;

    cudaFuncSetAttribute(ga_kernel, cudaFuncAttributeMaxDynamicSharedMemorySize,
                         SMEM_BYTES);

    detect_mask_kernel<<<1, 32>>>((const unsigned int*)mask);
    maskbits_kernel<<<(NB * NLQ * NWORDS) / 256, 256>>>(mask);
    ga_kernel<<<NCTAS, NTHREADS, SMEM_BYTES>>>(q, k, v, out);
}